// round 1
// baseline (speedup 1.0000x reference)
#include <cuda_runtime.h>
#include <cuda_bf16.h>

// LocallyConnected2d: out[b,o,h,w] = sum_{c,k} patch(x)[b,c,h,w,k] * W[o,c,h,w,k]
// x: [128, 64, 32, 32] f32
// weight: [1, 64, 64, 32, 32, 9] f32   (o, c, h, w, k)
// out: [128, 64, 32, 32] f32
//
// One block per spatial position (h,w): a 128x64x576 GEMM.
// Ci chunked by 4 (36 K-rows per chunk). Smem K-row-major so compute reads
// are vectorized LDS.128 along b (A) and o (B). Thread tile 8(b) x 4(o).

#define BATCH 128
#define CI    64
#define CO    64
#define HGT   32
#define WID   32
#define HWN   1024
#define CC    4            // Ci channels per chunk
#define KROWS (CC * 9)     // 36 K-rows per chunk

__global__ __launch_bounds__(256)
void lc2d_ffma_kernel(const float* __restrict__ x,
                      const float* __restrict__ wgt,
                      float* __restrict__ out) {
    const int hw = blockIdx.x;
    const int h  = hw >> 5;
    const int w  = hw & 31;

    __shared__ float As[KROWS * BATCH];  // [c'*9+k][b]   18432 B
    __shared__ float Bs[KROWS * CO];     // [c'*9+k][o]    9216 B

    const int tid = threadIdx.x;
    const int tx  = tid & 15;   // o group
    const int ty  = tid >> 4;   // b group
    const int b0  = ty * 8;
    const int o0  = tx * 4;

    float acc[8][4];
#pragma unroll
    for (int i = 0; i < 8; i++)
#pragma unroll
        for (int j = 0; j < 4; j++) acc[i][j] = 0.0f;

    for (int c0 = 0; c0 < CI; c0 += CC) {
        __syncthreads();   // previous chunk's reads done before overwrite

        // ---- Load A: x patches. One (b, c', p) triple -> 3 consecutive w's.
        // CC*3*128 = 1536 triples, 6 per thread.
#pragma unroll
        for (int t = tid; t < CC * 3 * BATCH; t += 256) {
            const int b  = t & 127;
            const int cp = t >> 7;        // 0..CC*3-1
            const int p  = cp % 3;
            const int c  = cp / 3;
            const int hh = h + p - 1;
            float v0 = 0.0f, v1 = 0.0f, v2 = 0.0f;
            if (hh >= 0 && hh < HGT) {
                const float* xr = x + (((size_t)b * CI + (c0 + c)) * HGT + hh) * WID;
                if (w - 1 >= 0) v0 = xr[w - 1];
                v1 = xr[w];
                if (w + 1 < WID) v2 = xr[w + 1];
            }
            const int base = (c * 9 + p * 3) * BATCH + b;
            As[base]             = v0;
            As[base + BATCH]     = v1;
            As[base + 2 * BATCH] = v2;
        }

        // ---- Load B: weights. One (c', o) pair -> 9 consecutive k's.
        // CC*64 = 256 pairs, 1 per thread.
#pragma unroll
        for (int t = tid; t < CC * CO; t += 256) {
            const int o = t & 63;
            const int c = t >> 6;
            const float* wr = wgt + (((size_t)(o * CI + c0 + c)) * HWN + hw) * 9;
#pragma unroll
            for (int k = 0; k < 9; k++)
                Bs[(c * 9 + k) * CO + o] = wr[k];
        }

        __syncthreads();

        // ---- Compute: 36 K-rows, 32 FFMA per row per thread.
#pragma unroll 6
        for (int r = 0; r < KROWS; r++) {
            const float4 a0 = *reinterpret_cast<const float4*>(&As[r * BATCH + b0]);
            const float4 a1 = *reinterpret_cast<const float4*>(&As[r * BATCH + b0 + 4]);
            const float4 bb = *reinterpret_cast<const float4*>(&Bs[r * CO + o0]);
            const float av[8] = {a0.x, a0.y, a0.z, a0.w, a1.x, a1.y, a1.z, a1.w};
            const float bv[4] = {bb.x, bb.y, bb.z, bb.w};
#pragma unroll
            for (int i = 0; i < 8; i++)
#pragma unroll
                for (int j = 0; j < 4; j++)
                    acc[i][j] = fmaf(av[i], bv[j], acc[i][j]);
        }
    }

    // ---- Write out: out[b][o][hw]. Scattered 4B stores (o stride = 1024 floats);
    // accepted this round (~30 us of write traffic, hidden under compute).
#pragma unroll
    for (int i = 0; i < 8; i++) {
        const size_t rowbase = ((size_t)(b0 + i) * CO + o0) * HWN + hw;
#pragma unroll
        for (int j = 0; j < 4; j++)
            out[rowbase + (size_t)j * HWN] = acc[i][j];
    }
}

extern "C" void kernel_launch(void* const* d_in, const int* in_sizes, int n_in,
                              void* d_out, int out_size) {
    const float* x   = (const float*)d_in[0];   // [128,64,32,32]
    const float* wgt = (const float*)d_in[1];   // [1,64,64,32,32,9]
    float* out = (float*)d_out;                 // [128,64,32,32]
    (void)in_sizes; (void)n_in; (void)out_size;
    lc2d_ffma_kernel<<<HWN, 256>>>(x, wgt, out);
}

// round 2
// speedup vs baseline: 1.7639x; 1.7639x over previous
#include <cuda_runtime.h>
#include <cuda_bf16.h>

// LocallyConnected2d: out[b,o,h,w] = sum_{c,k} patch(x)[b,c,h,w,k] * W[o,c,h,w,k]
// x: [128, 64, 32, 32] f32   weight: [1, 64, 64, 32, 32, 9] f32 (o,c,h,w,k)
// out: [128, 64, 32, 32] f32
//
// Pass 1: transpose x -> xT[c][h][w][b] (b contiguous) for coalesced A loads.
// Pass 2: 512 blocks, each = (h, w-pair). Per position a 128x64x576 GEMM,
//         Ci chunked by 4 (36 K-rows). 8(b)x8(o) register tile per thread,
//         256 threads cover 2 positions x 128b x 64o.

#define BATCH 128
#define CI    64
#define CO    64
#define HGT   32
#define WID   32
#define HWN   1024
#define CC    4            // Ci channels per chunk
#define KROWS (CC * 9)     // 36 K-rows per chunk

__device__ float g_xT[CI * HGT * WID * BATCH];   // 32 MB scratch: [c][h][w][b]

// ---------------- Pass 1: transpose x[b][c][h][w] -> xT[c][h][w][b] ----------
__global__ __launch_bounds__(256)
void lc2d_transpose_kernel(const float* __restrict__ x) {
    const int c = blockIdx.x >> 5;
    const int h = blockIdx.x & 31;
    __shared__ float tile[WID * (BATCH + 1)];   // [w][b], pad to kill conflicts
    const int tid = threadIdx.x;

#pragma unroll
    for (int it = 0; it < 16; it++) {
        const int idx = it * 256 + tid;
        const int b = idx >> 5;          // 0..127
        const int w = idx & 31;
        tile[w * (BATCH + 1) + b] = x[(((size_t)b * CI + c) * HGT + h) * WID + w];
    }
    __syncthreads();
#pragma unroll
    for (int it = 0; it < 16; it++) {
        const int idx = it * 256 + tid;
        const int w = idx >> 7;          // 0..31
        const int b = idx & 127;
        g_xT[(((size_t)c * HGT + h) * WID + w) * BATCH + b] = tile[w * (BATCH + 1) + b];
    }
}

// ---------------- Pass 2: main GEMM ------------------------------------------
__global__ __launch_bounds__(256)
void lc2d_ffma_kernel(const float* __restrict__ wgt,
                      float* __restrict__ out) {
    const int h     = blockIdx.x >> 4;
    const int wbase = (blockIdx.x & 15) * 2;    // positions wbase, wbase+1
    const int hw0   = h * WID + wbase;

    // A: [c'][p][q4][b] : 4 w-columns (wbase-1 .. wbase+2) shared by both positions
    __shared__ float As[CC * 3 * 4 * BATCH];          // 24576 B
    // B: [z][c'*9+k][o]
    __shared__ float Bs[2 * KROWS * CO];              // 18432 B

    const int tid = threadIdx.x;
    const int pz  = tid >> 7;          // which of the 2 positions
    const int tx  = tid & 7;           // o group
    const int ty  = (tid >> 3) & 15;   // b group
    const int b0  = ty * 8;
    const int o0  = tx * 8;

    float acc[8][8];
#pragma unroll
    for (int i = 0; i < 8; i++)
#pragma unroll
        for (int j = 0; j < 8; j++) acc[i][j] = 0.0f;

    for (int c0 = 0; c0 < CI; c0 += CC) {
        __syncthreads();   // previous chunk's reads done before overwrite

        // ---- Load A: coalesced float4 from xT. 48 rows x 128 b = 1536 float4.
#pragma unroll
        for (int it = 0; it < 6; it++) {
            const int idx  = it * 256 + tid;
            const int row  = idx >> 5;       // 0..47 : (c, p, q4)
            const int b4   = (idx & 31) * 4;
            const int c    = row / 12;
            const int rem  = row - c * 12;
            const int p    = rem >> 2;
            const int q4   = rem & 3;
            const int hh   = h + p - 1;
            const int ww   = wbase + q4 - 1;
            float4 v = make_float4(0.f, 0.f, 0.f, 0.f);
            if (hh >= 0 && hh < HGT && ww >= 0 && ww < WID) {
                v = *reinterpret_cast<const float4*>(
                    &g_xT[(((size_t)(c0 + c) * HGT + hh) * WID + ww) * BATCH + b4]);
            }
            *reinterpret_cast<float4*>(&As[row * BATCH + b4]) = v;
        }

        // ---- Load B: per (c', o) read 18 consecutive floats (both positions)
        //      as 9 aligned float2, scatter into Bs[z][c*9+k][o].
        {
            const int o = tid & 63;
            const int c = tid >> 6;      // 0..3
            const float* wr = wgt + ((size_t)(o * CI + c0 + c) * HWN + hw0) * 9;
#pragma unroll
            for (int j = 0; j < 9; j++) {
                const float2 v = *reinterpret_cast<const float2*>(wr + 2 * j);
                const int g0 = 2 * j;          // global k index 0..17
                const int z0 = g0 >= 9;
                Bs[((z0 ? 36 : 0) + c * 9 + (g0 - (z0 ? 9 : 0))) * CO + o] = v.x;
                const int g1 = 2 * j + 1;
                if (g1 < 18) {
                    const int z1 = g1 >= 9;
                    Bs[((z1 ? 36 : 0) + c * 9 + (g1 - (z1 ? 9 : 0))) * CO + o] = v.y;
                }
            }
        }

        __syncthreads();

        // ---- Compute: 36 K-rows x 64 FMA per thread.
        for (int c = 0; c < CC; c++) {
#pragma unroll
            for (int p = 0; p < 3; p++) {
#pragma unroll
                for (int q = 0; q < 3; q++) {
                    const int arow = ((c * 3 + p) * 4 + (q + pz)) * BATCH;
                    const int brow = (pz * KROWS + c * 9 + p * 3 + q) * CO;
                    const float4 a0 = *reinterpret_cast<const float4*>(&As[arow + b0]);
                    const float4 a1 = *reinterpret_cast<const float4*>(&As[arow + b0 + 4]);
                    const float4 w0 = *reinterpret_cast<const float4*>(&Bs[brow + o0]);
                    const float4 w1 = *reinterpret_cast<const float4*>(&Bs[brow + o0 + 4]);
                    const float av[8] = {a0.x, a0.y, a0.z, a0.w, a1.x, a1.y, a1.z, a1.w};
                    const float bv[8] = {w0.x, w0.y, w0.z, w0.w, w1.x, w1.y, w1.z, w1.w};
#pragma unroll
                    for (int i = 0; i < 8; i++)
#pragma unroll
                        for (int j = 0; j < 8; j++)
                            acc[i][j] = fmaf(av[i], bv[j], acc[i][j]);
                }
            }
        }
    }

    // ---- Write out[b][o][hw0+pz]. Scattered 4B stores (~5% of runtime).
    const int hw = hw0 + pz;
#pragma unroll
    for (int i = 0; i < 8; i++) {
        const size_t rowbase = ((size_t)(b0 + i) * CO + o0) * HWN + hw;
#pragma unroll
        for (int j = 0; j < 8; j++)
            out[rowbase + (size_t)j * HWN] = acc[i][j];
    }
}

extern "C" void kernel_launch(void* const* d_in, const int* in_sizes, int n_in,
                              void* d_out, int out_size) {
    const float* x   = (const float*)d_in[0];   // [128,64,32,32]
    const float* wgt = (const float*)d_in[1];   // [1,64,64,32,32,9]
    float* out = (float*)d_out;                 // [128,64,32,32]
    (void)in_sizes; (void)n_in; (void)out_size;
    lc2d_transpose_kernel<<<CI * HGT, 256>>>(x);
    lc2d_ffma_kernel<<<HGT * (WID / 2), 256>>>(wgt, out);
}

// round 4
// speedup vs baseline: 2.4663x; 1.3982x over previous
#include <cuda_runtime.h>
#include <cuda_bf16.h>
#include <cstdint>

// LocallyConnected2d via mma.sync m16n8k16 bf16x3 split-precision implicit GEMM.
// (tcgen05 unavailable: harness compiles at virtual arch compute_100.)
// out[b,o,h,w] = sum_{c,k} patch(x)[b,c,h,w,k] * W[o,c,h,w,k]
// x: [128,64,32,32] f32   weight: [1,64,64,32,32,9] f32   out: [128,64,32,32] f32
//
// Per position hw: D[128b x 64o] = A[128b x 576] * B[64o x 576]^T,
// bf16 split v = hi + lo, 3 passes (hh, hl, lh), fp32 accumulate.

#define BATCH 128
#define CI    64
#define CO    64
#define HGT   32
#define WID   32
#define HWN   1024
#define KC    64
#define NCHUNK 9

// smem layout (dynamic): A rows padded to 136 bf16 (272B), B rows to 72 bf16 (144B)
#define ASTR  136
#define BSTR  72
#define OFF_AH 0
#define OFF_AL 17408
#define OFF_BH 34816
#define OFF_BL 44032
#define DYN_BYTES 53248

__device__ uint32_t g_xhl[CI * HGT * WID * BATCH];   // 32 MB [c][h][w][b] packed {bf16 hi, lo}
__device__ float    g_outT[HWN * CO * BATCH];        // 32 MB [hw][o][b]

// ---------------- helpers ----------------------------------------------------
__device__ __forceinline__ uint32_t smem_u32(const void* p) {
    uint32_t a;
    asm("{ .reg .u64 t; cvta.to.shared.u64 t, %1; cvt.u32.u64 %0, t; }" : "=r"(a) : "l"(p));
    return a;
}
__device__ __forceinline__ uint32_t prmt(uint32_t a, uint32_t b, uint32_t s) {
    uint32_t r; asm("prmt.b32 %0, %1, %2, %3;" : "=r"(r) : "r"(a), "r"(b), "r"(s)); return r;
}
__device__ __forceinline__ void sts32(uint32_t a, uint32_t v) {
    asm volatile("st.shared.b32 [%0], %1;" :: "r"(a), "r"(v) : "memory");
}
__device__ __forceinline__ void sts16(uint32_t a, unsigned short v) {
    asm volatile("st.shared.b16 [%0], %1;" :: "r"(a), "h"(v) : "memory");
}
__device__ __forceinline__ uint32_t lds32(uint32_t a) {
    uint32_t v; asm volatile("ld.shared.b32 %0, [%1];" : "=r"(v) : "r"(a)); return v;
}
__device__ __forceinline__ void ldm4t(uint32_t* r, uint32_t addr) {
    asm volatile("ldmatrix.sync.aligned.m8n8.x4.trans.shared.b16 {%0,%1,%2,%3}, [%4];"
                 : "=r"(r[0]), "=r"(r[1]), "=r"(r[2]), "=r"(r[3]) : "r"(addr));
}
__device__ __forceinline__ void mma16816(float* d, const uint32_t* a, const uint32_t* b) {
    asm volatile("mma.sync.aligned.m16n8k16.row.col.f32.bf16.bf16.f32 "
                 "{%0,%1,%2,%3}, {%4,%5,%6,%7}, {%8,%9}, {%0,%1,%2,%3};"
                 : "+f"(d[0]), "+f"(d[1]), "+f"(d[2]), "+f"(d[3])
                 : "r"(a[0]), "r"(a[1]), "r"(a[2]), "r"(a[3]), "r"(b[0]), "r"(b[1]));
}
__device__ __forceinline__ uint32_t pack_hilo(float v) {
    __nv_bfloat16 h = __float2bfloat16(v);
    __nv_bfloat16 l = __float2bfloat16(v - __bfloat162float(h));
    return (uint32_t)__bfloat16_as_ushort(h) | ((uint32_t)__bfloat16_as_ushort(l) << 16);
}

// ---------------- Kernel 1: x -> g_xhl[c][h][w][b] ---------------------------
__global__ __launch_bounds__(256)
void prep_x_kernel(const float* __restrict__ x) {
    const int c = blockIdx.x >> 5;
    const int h = blockIdx.x & 31;
    __shared__ float tile[WID * 129];
    const int tid = threadIdx.x;
#pragma unroll
    for (int it = 0; it < 16; it++) {
        const int idx = it * 256 + tid;
        const int b = idx >> 5, w = idx & 31;
        tile[w * 129 + b] = x[(((size_t)b * CI + c) * HGT + h) * WID + w];
    }
    __syncthreads();
#pragma unroll
    for (int it = 0; it < 16; it++) {
        const int idx = it * 256 + tid;
        const int w = idx >> 7, b = idx & 127;
        g_xhl[(((size_t)c * HGT + h) * WID + w) * BATCH + b] = pack_hilo(tile[w * 129 + b]);
    }
}

// ---------------- Kernel 2: main MMA GEMM ------------------------------------
__global__ __launch_bounds__(256, 2)
void lc2d_mma_kernel(const float* __restrict__ wgt) {
    extern __shared__ __align__(16) char dyns[];
    __shared__ int rowsIdx[KC];

    const uint32_t dynb = smem_u32(dyns);
    const int hw  = blockIdx.x;
    const int h   = hw >> 5;
    const int w   = hw & 31;
    const int tid = threadIdx.x;
    const int wrp = tid >> 5;
    const int lane = tid & 31;

    const int wm = (wrp & 1) * 64;          // M offset (64-row half)
    const int wn = ((wrp >> 1) & 1) * 32;   // N offset (32-col half)
    const int wk = wrp >> 2;                // K-split group (ksteps 0,1 vs 2,3)

    // per-lane ldmatrix address components (trans, [k][m] storage)
    const int lm_r    = lane & 7;
    const int lm_koff = (lane & 16) ? 8 : 0;
    const int lm_moff = (lane & 8) ? 8 : 0;

    // B frag lane components ([n][k] storage)
    const int bn_lane = lane >> 2;          // n within 8
    const int bk_lane = (lane & 3) * 2;     // k within 8 (even)

    float acc[4][4][4];
#pragma unroll
    for (int mf = 0; mf < 4; mf++)
#pragma unroll
        for (int nf = 0; nf < 4; nf++)
#pragma unroll
            for (int c = 0; c < 4; c++) acc[mf][nf][c] = 0.0f;

    const int b2 = tid & 63;   // A-stage: this thread stages b = 2*b2, 2*b2+1
    const int kq = tid >> 6;   // A-stage: kk quarter (16 rows)

    for (int j = 0; j < NCHUNK; j++) {
        __syncthreads();   // previous chunk fully consumed

        if (tid < KC) {
            const int kk = j * KC + tid;
            const int c  = kk / 9;
            const int r9 = kk - c * 9;
            const int p  = r9 / 3;
            const int q  = r9 - p * 3;
            const int hh = h + p - 1;
            const int ww = w + q - 1;
            rowsIdx[tid] = (hh < 0 || hh >= HGT || ww < 0 || ww >= WID)
                         ? -1 : ((c * HGT + hh) * WID + ww);
        }
        __syncthreads();

        // ---- stage A: [kk][b] bf16, planes hi/lo -------------------------
#pragma unroll
        for (int t = 0; t < 16; t++) {
            const int kk  = kq * 16 + t;
            const int row = rowsIdx[kk];
            uint32_t v0 = 0u, v1 = 0u;
            if (row >= 0) {
                const uint2 v = *reinterpret_cast<const uint2*>(&g_xhl[(size_t)row * BATCH + 2 * b2]);
                v0 = v.x; v1 = v.y;
            }
            const uint32_t a = (uint32_t)kk * (ASTR * 2) + (uint32_t)b2 * 4;
            sts32(dynb + OFF_AH + a, prmt(v0, v1, 0x5410));
            sts32(dynb + OFF_AL + a, prmt(v0, v1, 0x7632));
        }

        // ---- stage B: weights direct from gmem, [o][kk] bf16 hi/lo -------
        {
            const int kk  = tid & 63;
            const int kkg = j * KC + kk;
            const int c   = kkg / 9;
            const int k   = kkg - c * 9;
            const size_t base = (size_t)c * (HWN * 9) + (size_t)hw * 9 + k;
#pragma unroll
            for (int it = 0; it < 16; it++) {
                const int o = it * 4 + (tid >> 6);
                const float v = wgt[(size_t)o * (CI * HWN * 9) + base];
                const __nv_bfloat16 hb = __float2bfloat16(v);
                const __nv_bfloat16 lb = __float2bfloat16(v - __bfloat162float(hb));
                const uint32_t a = (uint32_t)o * (BSTR * 2) + (uint32_t)kk * 2;
                sts16(dynb + OFF_BH + a, __bfloat16_as_ushort(hb));
                sts16(dynb + OFF_BL + a, __bfloat16_as_ushort(lb));
            }
        }
        __syncthreads();

        // ---- compute: this warp's 2 ksteps -------------------------------
#pragma unroll
        for (int s = 0; s < 2; s++) {
            const int kk0 = (wk * 2 + s) * 16;
            const uint32_t arow = (uint32_t)(kk0 + lm_koff + lm_r) * (ASTR * 2);

            uint32_t ah[4][4], bh[4][2], bl[4][2];
#pragma unroll
            for (int mf = 0; mf < 4; mf++)
                ldm4t(ah[mf], dynb + OFF_AH + arow + (uint32_t)(wm + mf * 16 + lm_moff) * 2);
#pragma unroll
            for (int nf = 0; nf < 4; nf++) {
                const uint32_t a = (uint32_t)(wn + nf * 8 + bn_lane) * (BSTR * 2)
                                 + (uint32_t)(kk0 + bk_lane) * 2;
                bh[nf][0] = lds32(dynb + OFF_BH + a);
                bh[nf][1] = lds32(dynb + OFF_BH + a + 16);
                bl[nf][0] = lds32(dynb + OFF_BL + a);
                bl[nf][1] = lds32(dynb + OFF_BL + a + 16);
            }
            // hh
#pragma unroll
            for (int mf = 0; mf < 4; mf++)
#pragma unroll
                for (int nf = 0; nf < 4; nf++)
                    mma16816(acc[mf][nf], ah[mf], bh[nf]);
            // hl
#pragma unroll
            for (int mf = 0; mf < 4; mf++)
#pragma unroll
                for (int nf = 0; nf < 4; nf++)
                    mma16816(acc[mf][nf], ah[mf], bl[nf]);
            // lh (Al overwrites Ah)
#pragma unroll
            for (int mf = 0; mf < 4; mf++)
                ldm4t(ah[mf], dynb + OFF_AL + arow + (uint32_t)(wm + mf * 16 + lm_moff) * 2);
#pragma unroll
            for (int mf = 0; mf < 4; mf++)
#pragma unroll
                for (int nf = 0; nf < 4; nf++)
                    mma16816(acc[mf][nf], ah[mf], bh[nf]);
        }
    }

    // ---- epilogue: K-split reduce via smem, then coalesced store ---------
    __syncthreads();                 // all frag reads done; reuse smem
    float* sOut = reinterpret_cast<float*>(dyns);   // [o][b], row stride 132

    if (wk == 1) {
#pragma unroll
        for (int mf = 0; mf < 4; mf++)
#pragma unroll
            for (int nf = 0; nf < 4; nf++)
#pragma unroll
                for (int c = 0; c < 4; c++) {
                    const int b = wm + mf * 16 + (lane >> 2) + ((c & 2) ? 8 : 0);
                    const int o = wn + nf * 8 + ((lane & 3) << 1) + (c & 1);
                    sOut[o * 132 + b] = acc[mf][nf][c];
                }
    }
    __syncthreads();
    if (wk == 0) {
#pragma unroll
        for (int mf = 0; mf < 4; mf++)
#pragma unroll
            for (int nf = 0; nf < 4; nf++)
#pragma unroll
                for (int c = 0; c < 4; c++) {
                    const int b = wm + mf * 16 + (lane >> 2) + ((c & 2) ? 8 : 0);
                    const int o = wn + nf * 8 + ((lane & 3) << 1) + (c & 1);
                    sOut[o * 132 + b] += acc[mf][nf][c];
                }
    }
    __syncthreads();

    float* dst = g_outT + (size_t)hw * (CO * BATCH);
#pragma unroll
    for (int it = 0; it < 8; it++) {
        const int idx = it * 256 + tid;       // 2048 float4
        const int o  = idx >> 5;
        const int b4 = (idx & 31) << 2;
        const float4 v = *reinterpret_cast<const float4*>(sOut + o * 132 + b4);
        *reinterpret_cast<float4*>(dst + o * BATCH + b4) = v;
    }
}

// ---------------- Kernel 3: g_outT[hw][o][b] -> out[b][o][hw] ----------------
__global__ __launch_bounds__(256)
void out_transpose_kernel(float* __restrict__ out) {
    const int o   = blockIdx.x >> 5;
    const int hw0 = (blockIdx.x & 31) * 32;
    __shared__ float tile[BATCH * 33];
    const int tid = threadIdx.x;
#pragma unroll
    for (int it = 0; it < 16; it++) {
        const int idx = it * 256 + tid;
        const int i = idx >> 7, b = idx & 127;
        tile[b * 33 + i] = g_outT[((size_t)(hw0 + i) * CO + o) * BATCH + b];
    }
    __syncthreads();
#pragma unroll
    for (int it = 0; it < 16; it++) {
        const int idx = it * 256 + tid;
        const int b = idx >> 5, i = idx & 31;
        out[((size_t)b * CO + o) * HWN + hw0 + i] = tile[b * 33 + i];
    }
}

// ---------------- launch -----------------------------------------------------
extern "C" void kernel_launch(void* const* d_in, const int* in_sizes, int n_in,
                              void* d_out, int out_size) {
    const float* x   = (const float*)d_in[0];
    const float* wgt = (const float*)d_in[1];
    float* out = (float*)d_out;
    (void)in_sizes; (void)n_in; (void)out_size;

    static int configured = 0;
    cudaFuncSetAttribute(lc2d_mma_kernel, cudaFuncAttributeMaxDynamicSharedMemorySize, DYN_BYTES);
    (void)configured;

    prep_x_kernel<<<CI * HGT, 256>>>(x);
    lc2d_mma_kernel<<<HWN, 256, DYN_BYTES>>>(wgt);
    out_transpose_kernel<<<CO * 32, 256>>>(out);
}

// round 6
// speedup vs baseline: 3.8073x; 1.5437x over previous
#include <cuda_runtime.h>
#include <cuda_bf16.h>
#include <cstdint>

// LocallyConnected2d via single-pass tf32 mma.sync m16n8k8 implicit GEMM with
// cp.async double-buffered staging.
// out[b,o,h,w] = sum_{c,k} patch(x)[b,c,h,w,k] * W[o,c,h,w,k]
// x: [128,64,32,32] f32   weight: [1,64,64,32,32,9] f32   out: [128,64,32,32] f32
//
// Per position hw: D[128b x 64o] = A[128b x 576] * B[64o x 576]^T in tf32
// (x RNA-rounded in prep; weights hardware-truncated), fp32 accumulate.
// R6 fix: B stage loop covers all 64 o-rows (was 16 -> rel_err 10.8).

#define BATCH 128
#define CI    64
#define CO    64
#define HGT   32
#define WID   32
#define HWN   1024
#define KC    64
#define NCHUNK 9

// smem stage: A [kk][b] rows padded to 136 floats (544B)
//             B [o][perm(k)] rows padded to 72 floats (288B)
#define ASTRB 544
#define BSTRB 288
#define OFF_B 34816                 // 64*544
#define STAGE 53248                 // 34816 + 64*288
#define DYN_BYTES (2 * STAGE)

__device__ float g_xT[CI * HGT * WID * BATCH];   // 16 MB [c][h][w][b], tf32-rounded
__device__ float g_outT[HWN * CO * BATCH];       // 32 MB [hw][o][b]

// ---------------- helpers ----------------------------------------------------
__device__ __forceinline__ uint32_t smem_u32(const void* p) {
    uint32_t a;
    asm("{ .reg .u64 t; cvta.to.shared.u64 t, %1; cvt.u32.u64 %0, t; }" : "=r"(a) : "l"(p));
    return a;
}
__device__ __forceinline__ float f2tf32(float v) {
    uint32_t r; asm("cvt.rna.tf32.f32 %0, %1;" : "=r"(r) : "f"(v));
    return __uint_as_float(r);
}
__device__ __forceinline__ uint32_t lds32(uint32_t a) {
    uint32_t v; asm volatile("ld.shared.b32 %0, [%1];" : "=r"(v) : "r"(a)); return v;
}
__device__ __forceinline__ void lds64(uint32_t a, uint32_t& lo, uint32_t& hi) {
    asm volatile("ld.shared.v2.b32 {%0,%1}, [%2];" : "=r"(lo), "=r"(hi) : "r"(a));
}
__device__ __forceinline__ void cp16(uint32_t dst, const void* src, int srcbytes) {
    asm volatile("cp.async.cg.shared.global [%0], [%1], 16, %2;"
                 :: "r"(dst), "l"(src), "r"(srcbytes) : "memory");
}
__device__ __forceinline__ void cp4(uint32_t dst, const void* src) {
    asm volatile("cp.async.ca.shared.global [%0], [%1], 4;"
                 :: "r"(dst), "l"(src) : "memory");
}
#define CP_COMMIT() asm volatile("cp.async.commit_group;" ::: "memory")
__device__ __forceinline__ void mma_tf32(float* d, const uint32_t* a, const uint32_t* b) {
    asm volatile("mma.sync.aligned.m16n8k8.row.col.f32.tf32.tf32.f32 "
                 "{%0,%1,%2,%3}, {%4,%5,%6,%7}, {%8,%9}, {%0,%1,%2,%3};"
                 : "+f"(d[0]), "+f"(d[1]), "+f"(d[2]), "+f"(d[3])
                 : "r"(a[0]), "r"(a[1]), "r"(a[2]), "r"(a[3]), "r"(b[0]), "r"(b[1]));
}

// ---------------- Kernel 1: x -> g_xT[c][h][w][b] (tf32-rounded) -------------
__global__ __launch_bounds__(256)
void prep_x_kernel(const float* __restrict__ x) {
    const int c = blockIdx.x >> 5;
    const int h = blockIdx.x & 31;
    __shared__ float tile[WID * 129];
    const int tid = threadIdx.x;
#pragma unroll
    for (int it = 0; it < 16; it++) {
        const int idx = it * 256 + tid;
        const int b = idx >> 5, w = idx & 31;
        tile[w * 129 + b] = x[(((size_t)b * CI + c) * HGT + h) * WID + w];
    }
    __syncthreads();
#pragma unroll
    for (int it = 0; it < 16; it++) {
        const int idx = it * 256 + tid;
        const int w = idx >> 7, b = idx & 127;
        g_xT[(((size_t)c * HGT + h) * WID + w) * BATCH + b] = f2tf32(tile[w * 129 + b]);
    }
}

// ---------------- Kernel 2: main MMA GEMM ------------------------------------
__global__ __launch_bounds__(256, 2)
void lc2d_mma_kernel(const float* __restrict__ wgt) {
    extern __shared__ __align__(16) char dyns[];
    __shared__ int rowsAll[NCHUNK * KC];

    const uint32_t dynb = smem_u32(dyns);
    const int hw  = blockIdx.x;
    const int h   = hw >> 5;
    const int w   = hw & 31;
    const int tid = threadIdx.x;
    const int wrp = tid >> 5;
    const int lane = tid & 31;

    const int wm = (wrp & 1) * 64;          // M offset
    const int wn = ((wrp >> 1) & 1) * 32;   // N offset
    const int wk = wrp >> 2;                // K-split half (K 0..31 vs 32..63)

    // ---- precompute kk -> xT row for all chunks --------------------------
    for (int t = tid; t < NCHUNK * KC; t += 256) {
        const int c  = t / 9;
        const int r9 = t - c * 9;
        const int p  = r9 / 3;
        const int q  = r9 - p * 3;
        const int hh = h + p - 1;
        const int ww = w + q - 1;
        rowsAll[t] = (hh < 0 || hh >= HGT || ww < 0 || ww >= WID)
                   ? -1 : ((c * HGT + hh) * WID + ww);
    }
    __syncthreads();

    float acc[4][4][4];
#pragma unroll
    for (int mf = 0; mf < 4; mf++)
#pragma unroll
        for (int nf = 0; nf < 4; nf++)
#pragma unroll
            for (int c = 0; c < 4; c++) acc[mf][nf][c] = 0.0f;

    // ---- prefetch chunk j into buffer base sb ----------------------------
    auto prefetch = [&](int j, uint32_t sb) {
        // A: 64kk x 128b = 2048 x 16B
#pragma unroll
        for (int it = 0; it < 8; it++) {
            const int u  = it * 256 + tid;
            const int kk = u >> 5;
            const int b4 = u & 31;
            const int row = rowsAll[j * KC + kk];
            const float* src = g_xT + (size_t)(row < 0 ? 0 : row) * BATCH + b4 * 4;
            cp16(sb + (uint32_t)kk * ASTRB + (uint32_t)b4 * 16, src, row < 0 ? 0 : 16);
        }
        // B: 64o x 64kk = 4096 x 4B, k-permuted dst (pairs (k, k+4) adjacent)
#pragma unroll
        for (int it = 0; it < 16; it++) {
            const int u   = it * 256 + tid;
            const int o   = u >> 6;
            const int kk  = u & 63;
            const int kkg = j * KC + kk;
            const int c   = kkg / 9;
            const int k   = kkg - c * 9;
            const int g   = kk >> 3;
            const int i   = kk & 7;
            const int pp  = g * 8 + (((i & 3) << 1) | (i >> 2));
            const float* src = wgt + ((size_t)o * CI + c) * (HWN * 9) + (size_t)hw * 9 + k;
            cp4(sb + OFF_B + (uint32_t)o * BSTRB + (uint32_t)pp * 4, src);
        }
    };

    prefetch(0, dynb);
    CP_COMMIT();

    for (int j = 0; j < NCHUNK; j++) {
        const uint32_t sb = dynb + (uint32_t)(j & 1) * STAGE;
        if (j + 1 < NCHUNK) prefetch(j + 1, dynb + (uint32_t)((j + 1) & 1) * STAGE);
        CP_COMMIT();
        if (j + 1 < NCHUNK) asm volatile("cp.async.wait_group 1;" ::: "memory");
        else                asm volatile("cp.async.wait_group 0;" ::: "memory");
        __syncthreads();

        // ---- compute: this warp's 4 k8-steps -----------------------------
#pragma unroll
        for (int s = 0; s < 4; s++) {
            const int kk0 = wk * 32 + s * 8;
            const uint32_t rA0 = sb + (uint32_t)(kk0 + (lane & 3)) * ASTRB
                               + (uint32_t)(wm + (lane >> 2)) * 4;
            const uint32_t rA1 = rA0 + 4 * ASTRB;   // k+4
            uint32_t a[4][4];
#pragma unroll
            for (int mf = 0; mf < 4; mf++) {
                a[mf][0] = lds32(rA0 + mf * 64);
                a[mf][1] = lds32(rA0 + mf * 64 + 32);
                a[mf][2] = lds32(rA1 + mf * 64);
                a[mf][3] = lds32(rA1 + mf * 64 + 32);
            }
            const uint32_t rB = sb + OFF_B + (uint32_t)(wn + (lane >> 2)) * BSTRB
                              + (uint32_t)(wk * 4 + s) * 32 + (uint32_t)(lane & 3) * 8;
            uint32_t bb[4][2];
#pragma unroll
            for (int nf = 0; nf < 4; nf++)
                lds64(rB + nf * 8 * BSTRB, bb[nf][0], bb[nf][1]);
#pragma unroll
            for (int mf = 0; mf < 4; mf++)
#pragma unroll
                for (int nf = 0; nf < 4; nf++)
                    mma_tf32(acc[mf][nf], a[mf], bb[nf]);
        }
        __syncthreads();   // chunk consumed; next iter may overwrite this buffer
    }

    // ---- epilogue: K-split reduce via smem, then coalesced store ---------
    float* sOut = reinterpret_cast<float*>(dyns);   // [o][b], stride 132
    if (wk == 1) {
#pragma unroll
        for (int mf = 0; mf < 4; mf++)
#pragma unroll
            for (int nf = 0; nf < 4; nf++)
#pragma unroll
                for (int c = 0; c < 4; c++) {
                    const int b = wm + mf * 16 + (lane >> 2) + ((c & 2) ? 8 : 0);
                    const int o = wn + nf * 8 + ((lane & 3) << 1) + (c & 1);
                    sOut[o * 132 + b] = acc[mf][nf][c];
                }
    }
    __syncthreads();
    if (wk == 0) {
#pragma unroll
        for (int mf = 0; mf < 4; mf++)
#pragma unroll
            for (int nf = 0; nf < 4; nf++)
#pragma unroll
                for (int c = 0; c < 4; c++) {
                    const int b = wm + mf * 16 + (lane >> 2) + ((c & 2) ? 8 : 0);
                    const int o = wn + nf * 8 + ((lane & 3) << 1) + (c & 1);
                    sOut[o * 132 + b] += acc[mf][nf][c];
                }
    }
    __syncthreads();

    float* dst = g_outT + (size_t)hw * (CO * BATCH);
#pragma unroll
    for (int it = 0; it < 8; it++) {
        const int idx = it * 256 + tid;       // 2048 float4
        const int o  = idx >> 5;
        const int b4 = (idx & 31) << 2;
        const float4 v = *reinterpret_cast<const float4*>(sOut + o * 132 + b4);
        *reinterpret_cast<float4*>(dst + o * BATCH + b4) = v;
    }
}

// ---------------- Kernel 3: g_outT[hw][o][b] -> out[b][o][hw] ----------------
__global__ __launch_bounds__(256)
void out_transpose_kernel(float* __restrict__ out) {
    const int o   = blockIdx.x >> 5;
    const int hw0 = (blockIdx.x & 31) * 32;
    __shared__ float tile[BATCH * 33];
    const int tid = threadIdx.x;
#pragma unroll
    for (int it = 0; it < 16; it++) {
        const int idx = it * 256 + tid;
        const int i = idx >> 7, b = idx & 127;
        tile[b * 33 + i] = g_outT[((size_t)(hw0 + i) * CO + o) * BATCH + b];
    }
    __syncthreads();
#pragma unroll
    for (int it = 0; it < 16; it++) {
        const int idx = it * 256 + tid;
        const int b = idx >> 5, i = idx & 31;
        out[((size_t)b * CO + o) * HWN + hw0 + i] = tile[b * 33 + i];
    }
}

// ---------------- launch -----------------------------------------------------
extern "C" void kernel_launch(void* const* d_in, const int* in_sizes, int n_in,
                              void* d_out, int out_size) {
    const float* x   = (const float*)d_in[0];
    const float* wgt = (const float*)d_in[1];
    float* out = (float*)d_out;
    (void)in_sizes; (void)n_in; (void)out_size;

    cudaFuncSetAttribute(lc2d_mma_kernel, cudaFuncAttributeMaxDynamicSharedMemorySize, DYN_BYTES);

    prep_x_kernel<<<CI * HGT, 256>>>(x);
    lc2d_mma_kernel<<<HWN, 256, DYN_BYTES>>>(wgt);
    out_transpose_kernel<<<CO * 32, 256>>>(out);
}